// round 2
// baseline (speedup 1.0000x reference)
#include <cuda_runtime.h>
#include <cstdint>

#define T_STEPS 100
#define U_UNITS 16
#define N_NEUR  1024
#define H_DIM   128

// ---------------- scratch (device globals; no allocation) ----------------
__device__ float   g_cur[U_UNITS * T_STEPS * N_NEUR];   // input currents  6.55 MB
__device__ uint8_t g_z[U_UNITS * T_STEPS * N_NEUR];     // spike outputs   1.64 MB
__device__ float   g_act[U_UNITS * N_NEUR];             // mean activity
__device__ float   g_h[H_DIM];                          // MLP hidden
__device__ float   g_conn[U_UNITS * U_UNITS];           // routing matrix
__device__ int     g_spk[U_UNITS];                      // per-unit spike counts
__device__ int     g_spk_total;

// ---------------- threefry2x32 (JAX-compatible) ----------------
__device__ __forceinline__ uint32_t rotl32(uint32_t x, int d) {
    return (x << d) | (x >> (32 - d));
}
__device__ __forceinline__ void threefry2x32(uint32_t k0, uint32_t k1,
                                             uint32_t x0, uint32_t x1,
                                             uint32_t& o0, uint32_t& o1) {
    uint32_t ks[3] = {k0, k1, k0 ^ k1 ^ 0x1BD11BDAu};
    x0 += ks[0]; x1 += ks[1];
    const int R[2][4] = {{13, 15, 26, 6}, {17, 29, 16, 24}};
    #pragma unroll
    for (int i = 0; i < 5; i++) {
        const int* r = R[i & 1];
        #pragma unroll
        for (int j = 0; j < 4; j++) {
            x0 += x1; x1 = rotl32(x1, r[j]); x1 ^= x0;
        }
        x0 += ks[(i + 1) % 3];
        x1 += ks[(i + 2) % 3] + (uint32_t)(i + 1);
    }
    o0 = x0; o1 = x1;
}

// ---------------- K1: input-current GEMM  cur[u,t,n] = spikes[t,:] . w_in[u,n,:] ----
// grid (8 n-tiles, 2 t-tiles, 16 units), block 128 threads; each thread owns 1 n, 50 t.
__global__ void __launch_bounds__(128) k1_incur(const float* __restrict__ spikes,
                                               const float* __restrict__ w_in) {
    const int u  = blockIdx.z;
    const int t0 = blockIdx.y * 50;
    const int n  = blockIdx.x * 128 + threadIdx.x;

    __shared__ float sm[50 * 128];   // spike tile [t][k]
    float acc[50];
    #pragma unroll
    for (int t = 0; t < 50; t++) acc[t] = 0.f;

    const float* wrow = w_in + ((size_t)u * N_NEUR + n) * N_NEUR;

    for (int k0 = 0; k0 < N_NEUR; k0 += 128) {
        // cooperative coalesced load of the spike tile
        #pragma unroll
        for (int r = 0; r < 50; r++)
            sm[r * 128 + threadIdx.x] = spikes[(t0 + r) * N_NEUR + k0 + threadIdx.x];
        __syncthreads();

        for (int kc = 0; kc < 128; kc += 4) {
            float4 w4 = *reinterpret_cast<const float4*>(wrow + k0 + kc);
            const float* sp = sm + kc;
            #pragma unroll
            for (int j = 0; j < 4; j++) {
                float w = (j == 0) ? w4.x : (j == 1) ? w4.y : (j == 2) ? w4.z : w4.w;
                #pragma unroll
                for (int t = 0; t < 50; t++)
                    acc[t] += w * sp[t * 128 + j];   // broadcast LDS across warp
            }
        }
        __syncthreads();
    }

    float* outp = g_cur + ((size_t)u * T_STEPS + t0) * N_NEUR + n;
    #pragma unroll
    for (int t = 0; t < 50; t++) outp[t * N_NEUR] = acc[t];
}

// ---------------- K2: LIF recurrent scan, one block per unit ----------------
__global__ void __launch_bounds__(1024) k2_scan(const float* __restrict__ w_rec) {
    const int u = blockIdx.x;
    const int n = threadIdx.x;
    const int warp = n >> 5, lane = n & 31;

    __shared__ unsigned mask[32];   // z of previous step, bitmask over 1024 neurons
    __shared__ int s_total;
    if (n == 0) s_total = 0;

    const float DTM   = 1e-3f * (1.0f / 20.0f);   // DT * TAU_MEM_INV = 5e-5
    const float DEC   = 1.0f - 1e-3f * (1.0f / 10.0f);  // 1 - DT * TAU_SYN_INV
    const float VLEAK = -70.0f, VTH = -55.0f, VRST = -70.0f;

    float v = VLEAK, i_syn = 0.0f;
    int count_prev = 0;       // z0 = 0 -> no recurrent term at t=0
    int emitted = 0;

    const float*   wr   = w_rec + ((size_t)u * N_NEUR + n) * N_NEUR;
    const float*   curp = g_cur + (size_t)u * T_STEPS * N_NEUR + n;
    uint8_t*       zp   = g_z   + (size_t)u * T_STEPS * N_NEUR + n;

    float cur_t = curp[0];
    __syncthreads();   // s_total init visible; mask not read until written

    for (int t = 0; t < T_STEPS; t++) {
        float v_dec = v + DTM * ((VLEAK - v) + i_syn);
        float i_dec = i_syn * DEC;
        bool  z     = (v_dec - VTH) > 0.0f;
        v = z ? VRST : v_dec;
        emitted += (int)z;
        zp[t * N_NEUR] = z ? (uint8_t)1 : (uint8_t)0;

        // recurrent term from PREVIOUS step's spikes (carry z) — sparse gather
        float rec = 0.0f;
        if (count_prev > 0) {
            #pragma unroll 1
            for (int w = 0; w < 32; w++) {
                unsigned m = mask[w];
                while (m) {
                    int b = __ffs(m) - 1;
                    rec += wr[w * 32 + b];
                    m &= m - 1;
                }
            }
        }
        i_syn = i_dec + cur_t + rec;

        // prefetch next input current before the barriers
        float cur_next = (t + 1 < T_STEPS) ? curp[(t + 1) * N_NEUR] : 0.0f;

        __syncthreads();                       // all reads of old mask done
        unsigned bal = __ballot_sync(0xFFFFFFFFu, z);
        if (lane == 0) mask[warp] = bal;
        __syncthreads();                       // new mask published
        count_prev = 0;
        #pragma unroll
        for (int w = 0; w < 32; w++) count_prev += __popc(mask[w]);

        cur_t = cur_next;
    }

    g_act[u * N_NEUR + n] = (float)emitted * (1.0f / T_STEPS);
    atomicAdd(&s_total, emitted);
    __syncthreads();
    if (n == 0) g_spk[u] = s_total;
}

// ---------------- K3a: hidden layer  h = relu(activity @ cw1.T + cb1) ----------------
__global__ void __launch_bounds__(256) k3a_hidden(const float* __restrict__ cw1,
                                                  const float* __restrict__ cb1) {
    const int hh = blockIdx.x;     // 128 blocks
    const float* row = cw1 + (size_t)hh * (U_UNITS * N_NEUR);
    float s = 0.0f;
    for (int j = threadIdx.x; j < U_UNITS * N_NEUR; j += blockDim.x)
        s += row[j] * g_act[j];
    __shared__ float red[8];
    #pragma unroll
    for (int o = 16; o > 0; o >>= 1) s += __shfl_down_sync(0xFFFFFFFFu, s, o);
    if ((threadIdx.x & 31) == 0) red[threadIdx.x >> 5] = s;
    __syncthreads();
    if (threadIdx.x == 0) {
        float v = 0.0f;
        #pragma unroll
        for (int w = 0; w < 8; w++) v += red[w];
        g_h[hh] = fmaxf(v + cb1[hh], 0.0f);
    }
}

// ---------------- K3b: logits -> sigmoid -> threefry Bernoulli -> conn; spike total ---
__global__ void __launch_bounds__(256) k3b_conn(const float* __restrict__ cw2,
                                                const float* __restrict__ cb2) {
    const int j = threadIdx.x;    // 256 = U*U
    __shared__ float hs[H_DIM];
    if (j < H_DIM) hs[j] = g_h[j];
    __syncthreads();

    float logit = cb2[j];
    const float* row = cw2 + (size_t)j * H_DIM;
    #pragma unroll 4
    for (int k = 0; k < H_DIM; k++) logit += hs[k] * row[k];
    float p = 1.0f / (1.0f + expf(-logit));

    // jax.random.uniform(key(42), (16,16)): key=(0,42), counts=iota(256) split in half
    uint32_t c = (j < 128) ? (uint32_t)j : (uint32_t)(j - 128);
    uint32_t o0, o1;
    threefry2x32(0u, 42u, c, c + 128u, o0, o1);
    uint32_t bits = (j < 128) ? o0 : o1;
    float uf = __uint_as_float((bits >> 9) | 0x3F800000u) - 1.0f;   // [0,1)
    uf = fmaxf(uf, 0.0f);
    g_conn[j] = (uf < p) ? 1.0f : 0.0f;

    if (j == 0) {
        int tot = 0;
        #pragma unroll
        for (int u2 = 0; u2 < U_UNITS; u2++) tot += g_spk[u2];
        g_spk_total = tot;
    }
}

// ---------------- K4: routed/applied/combined + residual ----------------
__global__ void __launch_bounds__(256) k4_out(const float* __restrict__ spikes,
                                              const float* __restrict__ unit_w,
                                              float* __restrict__ out) {
    int idx = blockIdx.x * blockDim.x + threadIdx.x;
    if (idx >= T_STEPS * N_NEUR) return;
    int t = idx / N_NEUR, m = idx % N_NEUR;

    float c = 0.0f;
    if (g_spk_total != 0) {
        // generic fallback path (only taken if any unit actually spiked)
        for (int j = 0; j < U_UNITS; j++) {
            float cj = 0.0f;
            for (int nn = 0; nn < N_NEUR; nn++) {
                float r = 0.0f;
                #pragma unroll
                for (int i2 = 0; i2 < U_UNITS; i2++)
                    r += g_conn[i2 * U_UNITS + j] *
                         (float)g_z[((size_t)i2 * T_STEPS + t) * N_NEUR + nn];
                cj += r * unit_w[((size_t)j * N_NEUR + nn) * N_NEUR + m];
            }
            c += cj;
        }
        c *= (1.0f / U_UNITS);
    }
    out[idx] = c + 1.5f * spikes[idx];
}

// ---------------- launch ----------------
extern "C" void kernel_launch(void* const* d_in, const int* in_sizes, int n_in,
                              void* d_out, int out_size) {
    const float* spikes = (const float*)d_in[0];   // [100,1024]
    const float* w_in   = (const float*)d_in[1];   // [16,1024,1024]
    const float* w_rec  = (const float*)d_in[2];   // [16,1024,1024]
    const float* unit_w = (const float*)d_in[3];   // [16,1024,1024]
    const float* cw1    = (const float*)d_in[4];   // [128,16384]
    const float* cb1    = (const float*)d_in[5];   // [128]
    const float* cw2    = (const float*)d_in[6];   // [256,128]
    const float* cb2    = (const float*)d_in[7];   // [256]
    float* out = (float*)d_out;                    // [100,1024]

    k1_incur<<<dim3(8, 2, 16), 128>>>(spikes, w_in);
    k2_scan<<<16, 1024>>>(w_rec);
    k3a_hidden<<<128, 256>>>(cw1, cb1);
    k3b_conn<<<1, 256>>>(cw2, cb2);
    k4_out<<<(T_STEPS * N_NEUR + 255) / 256, 256>>>(spikes, unit_w, out);
}

// round 3
// speedup vs baseline: 16.6783x; 16.6783x over previous
#include <cuda_runtime.h>
#include <cstdint>

#define T_STEPS 100
#define U_UNITS 16
#define N_NEUR  1024
#define H_DIM   128

// ---------------- scratch (device globals; no allocation) ----------------
__device__ float   g_cur[U_UNITS * T_STEPS * N_NEUR];   // input currents
__device__ uint8_t g_z[U_UNITS * T_STEPS * N_NEUR];     // spike outputs
__device__ float   g_act[U_UNITS * N_NEUR];             // mean activity
__device__ float   g_h[H_DIM];                          // MLP hidden
__device__ float   g_conn[U_UNITS * U_UNITS];           // routing matrix
__device__ int     g_spk[U_UNITS];                      // per-unit spike counts
__device__ int     g_spk_total;
__device__ float   g_partialA[2048];                    // per-block max row-L1 of w_in
__device__ float   g_partialB[2048];                    // per-block max |input|
__device__ int     g_skip;                              // 1 => provably zero spikes

// ---------------- threefry2x32 (JAX-compatible) ----------------
__device__ __forceinline__ uint32_t rotl32(uint32_t x, int d) {
    return (x << d) | (x >> (32 - d));
}
__device__ __forceinline__ void threefry2x32(uint32_t k0, uint32_t k1,
                                             uint32_t x0, uint32_t x1,
                                             uint32_t& o0, uint32_t& o1) {
    uint32_t ks[3] = {k0, k1, k0 ^ k1 ^ 0x1BD11BDAu};
    x0 += ks[0]; x1 += ks[1];
    const int R[2][4] = {{13, 15, 26, 6}, {17, 29, 16, 24}};
    #pragma unroll
    for (int i = 0; i < 5; i++) {
        const int* r = R[i & 1];
        #pragma unroll
        for (int j = 0; j < 4; j++) {
            x0 += x1; x1 = rotl32(x1, r[j]); x1 ^= x0;
        }
        x0 += ks[(i + 1) % 3];
        x1 += ks[(i + 2) % 3] + (uint32_t)(i + 1);
    }
    o0 = x0; o1 = x1;
}

// ---------------- K0a: no-spike bound statistics ----------------
// 2048 blocks x 256 threads. Each block: 8 warps, one w_in row (1024 f32) per warp
// -> max row L1 norm; plus a 50-element slice of the input -> max |x|.
__global__ void __launch_bounds__(256) k0a_bound(const float* __restrict__ w_in,
                                                 const float* __restrict__ spikes) {
    const int warp = threadIdx.x >> 5, lane = threadIdx.x & 31;
    const int row = blockIdx.x * 8 + warp;              // 0..16383 = u*1024+n
    const float4* rp = reinterpret_cast<const float4*>(w_in + (size_t)row * N_NEUR);

    float s = 0.0f;
    #pragma unroll
    for (int i = 0; i < 8; i++) {
        float4 v = rp[lane + i * 32];
        s += fabsf(v.x) + fabsf(v.y) + fabsf(v.z) + fabsf(v.w);
    }
    #pragma unroll
    for (int o = 16; o > 0; o >>= 1) s += __shfl_down_sync(0xFFFFFFFFu, s, o);

    __shared__ float smL1[8];
    __shared__ float smX[8];
    if (lane == 0) smL1[warp] = s;

    // input slice: 50 elements per block (2048*50 >= 102400)
    float xm = 0.0f;
    {
        int idx = blockIdx.x * 50 + threadIdx.x;
        if (threadIdx.x < 50 && idx < T_STEPS * N_NEUR)
            xm = fabsf(spikes[idx]);
    }
    #pragma unroll
    for (int o = 16; o > 0; o >>= 1) xm = fmaxf(xm, __shfl_down_sync(0xFFFFFFFFu, xm, o));
    if (lane == 0) smX[warp] = xm;
    __syncthreads();

    if (threadIdx.x == 0) {
        float l1 = 0.0f, xmax = 0.0f;
        #pragma unroll
        for (int w = 0; w < 8; w++) { l1 = fmaxf(l1, smL1[w]); xmax = fmaxf(xmax, smX[w]); }
        g_partialA[blockIdx.x] = l1;
        g_partialB[blockIdx.x] = xmax;
    }
}

// ---------------- K0c: finalize the no-spike proof flag ----------------
__global__ void __launch_bounds__(1024) k0c_flag() {
    const int t = threadIdx.x;
    float a = fmaxf(g_partialA[t], g_partialA[t + 1024]);
    float b = fmaxf(g_partialB[t], g_partialB[t + 1024]);
    __shared__ float sa[32], sb[32];
    #pragma unroll
    for (int o = 16; o > 0; o >>= 1) {
        a = fmaxf(a, __shfl_down_sync(0xFFFFFFFFu, a, o));
        b = fmaxf(b, __shfl_down_sync(0xFFFFFFFFu, b, o));
    }
    if ((t & 31) == 0) { sa[t >> 5] = a; sb[t >> 5] = b; }
    __syncthreads();
    if (t == 0) {
        float L1 = 0.0f, X = 0.0f;
        #pragma unroll
        for (int w = 0; w < 32; w++) { L1 = fmaxf(L1, sa[w]); X = fmaxf(X, sb[w]); }
        // Until the first spike z==0, so |i_t| <= t * X * L1 and
        // v_T - V_LEAK <= DT*TAU_MEM_INV * sum_{t<100} t*X*L1 = 5e-5*4950*X*L1.
        // If that stays < 14 << 15 = V_TH - V_LEAK, no neuron can ever spike
        // (NaN-safe: NaN comparison -> false -> fallback path).
        float bound = 5e-5f * 4950.0f * X * L1;
        g_skip = (bound < 14.0f) ? 1 : 0;
    }
}

// ---------------- K1: input-current GEMM (fallback path) ----------------
__global__ void __launch_bounds__(128) k1_incur(const float* __restrict__ spikes,
                                               const float* __restrict__ w_in) {
    if (g_skip) return;
    const int u  = blockIdx.z;
    const int t0 = blockIdx.y * 50;
    const int n  = blockIdx.x * 128 + threadIdx.x;

    __shared__ float sm[50 * 128];
    float acc[50];
    #pragma unroll
    for (int t = 0; t < 50; t++) acc[t] = 0.f;

    const float* wrow = w_in + ((size_t)u * N_NEUR + n) * N_NEUR;

    for (int k0 = 0; k0 < N_NEUR; k0 += 128) {
        #pragma unroll
        for (int r = 0; r < 50; r++)
            sm[r * 128 + threadIdx.x] = spikes[(t0 + r) * N_NEUR + k0 + threadIdx.x];
        __syncthreads();

        for (int kc = 0; kc < 128; kc += 4) {
            float4 w4 = *reinterpret_cast<const float4*>(wrow + k0 + kc);
            const float* sp = sm + kc;
            #pragma unroll
            for (int j = 0; j < 4; j++) {
                float w = (j == 0) ? w4.x : (j == 1) ? w4.y : (j == 2) ? w4.z : w4.w;
                #pragma unroll
                for (int t = 0; t < 50; t++)
                    acc[t] += w * sp[t * 128 + j];
            }
        }
        __syncthreads();
    }

    float* outp = g_cur + ((size_t)u * T_STEPS + t0) * N_NEUR + n;
    #pragma unroll
    for (int t = 0; t < 50; t++) outp[t * N_NEUR] = acc[t];
}

// ---------------- K2: LIF recurrent scan (fallback path) ----------------
__global__ void __launch_bounds__(1024) k2_scan(const float* __restrict__ w_rec) {
    if (g_skip) return;
    const int u = blockIdx.x;
    const int n = threadIdx.x;
    const int warp = n >> 5, lane = n & 31;

    __shared__ unsigned mask[32];
    __shared__ int s_total;
    if (n == 0) s_total = 0;

    const float DTM   = 1e-3f * (1.0f / 20.0f);
    const float DEC   = 1.0f - 1e-3f * (1.0f / 10.0f);
    const float VLEAK = -70.0f, VTH = -55.0f, VRST = -70.0f;

    float v = VLEAK, i_syn = 0.0f;
    int count_prev = 0;
    int emitted = 0;

    const float* wr   = w_rec + ((size_t)u * N_NEUR + n) * N_NEUR;
    const float* curp = g_cur + (size_t)u * T_STEPS * N_NEUR + n;
    uint8_t*     zp   = g_z   + (size_t)u * T_STEPS * N_NEUR + n;

    float cur_t = curp[0];
    __syncthreads();

    for (int t = 0; t < T_STEPS; t++) {
        float v_dec = v + DTM * ((VLEAK - v) + i_syn);
        float i_dec = i_syn * DEC;
        bool  z     = (v_dec - VTH) > 0.0f;
        v = z ? VRST : v_dec;
        emitted += (int)z;
        zp[t * N_NEUR] = z ? (uint8_t)1 : (uint8_t)0;

        float rec = 0.0f;
        if (count_prev > 0) {
            #pragma unroll 1
            for (int w = 0; w < 32; w++) {
                unsigned m = mask[w];
                while (m) {
                    int b = __ffs(m) - 1;
                    rec += wr[w * 32 + b];
                    m &= m - 1;
                }
            }
        }
        i_syn = i_dec + cur_t + rec;

        float cur_next = (t + 1 < T_STEPS) ? curp[(t + 1) * N_NEUR] : 0.0f;

        __syncthreads();
        unsigned bal = __ballot_sync(0xFFFFFFFFu, z);
        if (lane == 0) mask[warp] = bal;
        __syncthreads();
        count_prev = 0;
        #pragma unroll
        for (int w = 0; w < 32; w++) count_prev += __popc(mask[w]);

        cur_t = cur_next;
    }

    g_act[u * N_NEUR + n] = (float)emitted * (1.0f / T_STEPS);
    atomicAdd(&s_total, emitted);
    __syncthreads();
    if (n == 0) g_spk[u] = s_total;
}

// ---------------- K3a: hidden layer (fallback path) ----------------
__global__ void __launch_bounds__(256) k3a_hidden(const float* __restrict__ cw1,
                                                  const float* __restrict__ cb1) {
    if (g_skip) return;
    const int hh = blockIdx.x;
    const float* row = cw1 + (size_t)hh * (U_UNITS * N_NEUR);
    float s = 0.0f;
    for (int j = threadIdx.x; j < U_UNITS * N_NEUR; j += blockDim.x)
        s += row[j] * g_act[j];
    __shared__ float red[8];
    #pragma unroll
    for (int o = 16; o > 0; o >>= 1) s += __shfl_down_sync(0xFFFFFFFFu, s, o);
    if ((threadIdx.x & 31) == 0) red[threadIdx.x >> 5] = s;
    __syncthreads();
    if (threadIdx.x == 0) {
        float v = 0.0f;
        #pragma unroll
        for (int w = 0; w < 8; w++) v += red[w];
        g_h[hh] = fmaxf(v + cb1[hh], 0.0f);
    }
}

// ---------------- K3b: conn matrix + spike total (fallback path) ----------------
__global__ void __launch_bounds__(256) k3b_conn(const float* __restrict__ cw2,
                                                const float* __restrict__ cb2) {
    if (g_skip) return;
    const int j = threadIdx.x;
    __shared__ float hs[H_DIM];
    if (j < H_DIM) hs[j] = g_h[j];
    __syncthreads();

    float logit = cb2[j];
    const float* row = cw2 + (size_t)j * H_DIM;
    #pragma unroll 4
    for (int k = 0; k < H_DIM; k++) logit += hs[k] * row[k];
    float p = 1.0f / (1.0f + expf(-logit));

    uint32_t c = (j < 128) ? (uint32_t)j : (uint32_t)(j - 128);
    uint32_t o0, o1;
    threefry2x32(0u, 42u, c, c + 128u, o0, o1);
    uint32_t bits = (j < 128) ? o0 : o1;
    float uf = __uint_as_float((bits >> 9) | 0x3F800000u) - 1.0f;
    uf = fmaxf(uf, 0.0f);
    g_conn[j] = (uf < p) ? 1.0f : 0.0f;

    if (j == 0) {
        int tot = 0;
        #pragma unroll
        for (int u2 = 0; u2 < U_UNITS; u2++) tot += g_spk[u2];
        g_spk_total = tot;
    }
}

// ---------------- K4: output ----------------
__global__ void __launch_bounds__(256) k4_out(const float* __restrict__ spikes,
                                              const float* __restrict__ unit_w,
                                              float* __restrict__ out) {
    int idx = blockIdx.x * blockDim.x + threadIdx.x;
    if (idx >= T_STEPS * N_NEUR) return;

    if (g_skip) {                         // proven: zero spikes -> combined == 0
        out[idx] = 1.5f * spikes[idx];
        return;
    }

    int t = idx / N_NEUR, m = idx % N_NEUR;
    float c = 0.0f;
    if (g_spk_total != 0) {
        for (int j = 0; j < U_UNITS; j++) {
            float cj = 0.0f;
            for (int nn = 0; nn < N_NEUR; nn++) {
                float r = 0.0f;
                #pragma unroll
                for (int i2 = 0; i2 < U_UNITS; i2++)
                    r += g_conn[i2 * U_UNITS + j] *
                         (float)g_z[((size_t)i2 * T_STEPS + t) * N_NEUR + nn];
                cj += r * unit_w[((size_t)j * N_NEUR + nn) * N_NEUR + m];
            }
            c += cj;
        }
        c *= (1.0f / U_UNITS);
    }
    out[idx] = c + 1.5f * spikes[idx];
}

// ---------------- launch ----------------
extern "C" void kernel_launch(void* const* d_in, const int* in_sizes, int n_in,
                              void* d_out, int out_size) {
    const float* spikes = (const float*)d_in[0];   // [100,1024]
    const float* w_in   = (const float*)d_in[1];   // [16,1024,1024]
    const float* w_rec  = (const float*)d_in[2];   // [16,1024,1024]
    const float* unit_w = (const float*)d_in[3];   // [16,1024,1024]
    const float* cw1    = (const float*)d_in[4];   // [128,16384]
    const float* cb1    = (const float*)d_in[5];   // [128]
    const float* cw2    = (const float*)d_in[6];   // [256,128]
    const float* cb2    = (const float*)d_in[7];   // [256]
    float* out = (float*)d_out;                    // [100,1024]

    k0a_bound<<<2048, 256>>>(w_in, spikes);
    k0c_flag<<<1, 1024>>>();
    k1_incur<<<dim3(8, 2, 16), 128>>>(spikes, w_in);
    k2_scan<<<16, 1024>>>(w_rec);
    k3a_hidden<<<128, 256>>>(cw1, cb1);
    k3b_conn<<<1, 256>>>(cw2, cb2);
    k4_out<<<(T_STEPS * N_NEUR + 255) / 256, 256>>>(spikes, unit_w, out);
}

// round 4
// speedup vs baseline: 25.0802x; 1.5038x over previous
#include <cuda_runtime.h>
#include <cstdint>
#include <math_constants.h>

#define T_STEPS 100
#define U_UNITS 16
#define N_NEUR  1024
#define H_DIM   128
#define NBLK    148
#define NTHR    1024
#define NWARP_G (NBLK * 32)          // 4736 global warps

// ---------------- scratch (device globals; no allocation) ----------------
__device__ float   g_cur[U_UNITS * T_STEPS * N_NEUR];
__device__ uint8_t g_z[U_UNITS * T_STEPS * N_NEUR];
__device__ float   g_act[U_UNITS * N_NEUR];
__device__ float   g_h[H_DIM];
__device__ float   g_conn[U_UNITS * U_UNITS];
__device__ int     g_spk[U_UNITS];
__device__ int     g_spk_total;
__device__ float   g_partialA[NBLK];     // per-block max row-L1 of w_in
__device__ float   g_partialB[NBLK];     // per-block max |input|
// software grid barrier state (epoch-based; replay-safe: epoch only grows)
__device__ int     g_bar_count = 0;
__device__ int     g_bar_epoch = 0;

// ---------------- grid barrier (all NBLK blocks co-resident) ----------------
__device__ __forceinline__ void grid_barrier() {
    __syncthreads();
    if (threadIdx.x == 0) {
        __threadfence();                               // publish this block's writes
        int e = *(volatile int*)&g_bar_epoch;          // epoch before arrival
        int t = atomicAdd(&g_bar_count, 1);
        if (t == NBLK - 1) {
            g_bar_count = 0;
            __threadfence();
            atomicAdd(&g_bar_epoch, 1);
        } else {
            while (*(volatile int*)&g_bar_epoch == e) { }
        }
        __threadfence();                               // acquire others' writes
    }
    __syncthreads();
}

// ---------------- threefry2x32 (JAX-compatible) ----------------
__device__ __forceinline__ uint32_t rotl32(uint32_t x, int d) {
    return (x << d) | (x >> (32 - d));
}
__device__ __forceinline__ void threefry2x32(uint32_t k0, uint32_t k1,
                                             uint32_t x0, uint32_t x1,
                                             uint32_t& o0, uint32_t& o1) {
    uint32_t ks[3] = {k0, k1, k0 ^ k1 ^ 0x1BD11BDAu};
    x0 += ks[0]; x1 += ks[1];
    const int R[2][4] = {{13, 15, 26, 6}, {17, 29, 16, 24}};
    #pragma unroll
    for (int i = 0; i < 5; i++) {
        const int* r = R[i & 1];
        #pragma unroll
        for (int j = 0; j < 4; j++) {
            x0 += x1; x1 = rotl32(x1, r[j]); x1 ^= x0;
        }
        x0 += ks[(i + 1) % 3];
        x1 += ks[(i + 2) % 3] + (uint32_t)(i + 1);
    }
    o0 = x0; o1 = x1;
}

// ============================ THE mega-kernel ============================
__global__ void __launch_bounds__(NTHR, 1)
mega(const float* __restrict__ spikes, const float* __restrict__ w_in,
     const float* __restrict__ w_rec,  const float* __restrict__ unit_w,
     const float* __restrict__ cw1,    const float* __restrict__ cb1,
     const float* __restrict__ cw2,    const float* __restrict__ cb2,
     float* __restrict__ out) {
    const int tid  = threadIdx.x;
    const int bid  = blockIdx.x;
    const int warp = tid >> 5, lane = tid & 31;
    const int gtid = bid * NTHR + tid;

    __shared__ float smA[32], smB[32];
    __shared__ float s_red[32];

    // ---------------- Phase A: no-spike bound statistics ----------------
    {
        const int gw = bid * 32 + warp;
        float l1max = 0.0f;
        for (int row = gw; row < U_UNITS * N_NEUR; row += NWARP_G) {
            const float4* rp = reinterpret_cast<const float4*>(w_in + (size_t)row * N_NEUR);
            float s = 0.0f;
            #pragma unroll
            for (int i = 0; i < 8; i++) {
                float4 v = rp[lane + i * 32];
                s += fabsf(v.x) + fabsf(v.y) + fabsf(v.z) + fabsf(v.w);
            }
            #pragma unroll
            for (int o = 16; o > 0; o >>= 1) s += __shfl_down_sync(0xFFFFFFFFu, s, o);
            if (lane == 0) {
                if (!(s == s)) s = CUDART_INF_F;        // NaN => force fallback
                l1max = fmaxf(l1max, s);
            }
        }
        float xmax = 0.0f;
        if (gtid < (T_STEPS * N_NEUR) / 4) {
            float4 v = reinterpret_cast<const float4*>(spikes)[gtid];
            float m = fmaxf(fmaxf(fabsf(v.x), fabsf(v.y)), fmaxf(fabsf(v.z), fabsf(v.w)));
            if (!(m == m)) m = CUDART_INF_F;
            xmax = m;
        }
        #pragma unroll
        for (int o = 16; o > 0; o >>= 1) xmax = fmaxf(xmax, __shfl_down_sync(0xFFFFFFFFu, xmax, o));
        if (lane == 0) { smA[warp] = l1max; smB[warp] = xmax; }
        __syncthreads();
        if (tid == 0) {
            float A = 0.0f, B = 0.0f;
            #pragma unroll
            for (int w = 0; w < 32; w++) { A = fmaxf(A, smA[w]); B = fmaxf(B, smB[w]); }
            g_partialA[bid] = A;
            g_partialB[bid] = B;
        }
    }

    grid_barrier();

    // every block redundantly reduces the 148 partials -> identical skip decision
    __shared__ int s_skip;
    {
        float A = 0.0f, B = 0.0f;
        if (tid < NBLK) { A = g_partialA[tid]; B = g_partialB[tid]; }
        #pragma unroll
        for (int o = 16; o > 0; o >>= 1) {
            A = fmaxf(A, __shfl_down_sync(0xFFFFFFFFu, A, o));
            B = fmaxf(B, __shfl_down_sync(0xFFFFFFFFu, B, o));
        }
        if (lane == 0) { smA[warp] = A; smB[warp] = B; }
        __syncthreads();
        if (tid == 0) {
            float L1 = 0.0f, X = 0.0f;
            #pragma unroll
            for (int w = 0; w < 5; w++) { L1 = fmaxf(L1, smA[w]); X = fmaxf(X, smB[w]); }
            // Until the first spike z==0, so |i_t| <= t*X*L1 and
            // v_T - V_LEAK <= 5e-5 * (sum_{t<100} t) * X * L1 = 5e-5*4950*X*L1.
            // If < 14 << 15 = V_TH - V_LEAK, no neuron can ever spike.
            // (NaN propagated to INF above => comparison false => fallback.)
            float bound = 5e-5f * 4950.0f * X * L1;
            s_skip = (bound < 14.0f) ? 1 : 0;
        }
        __syncthreads();
    }

    // ---------------- Skip path: out = 1.5*spikes, done ----------------
    if (s_skip) {
        const float4* sp4 = reinterpret_cast<const float4*>(spikes);
        float4* out4 = reinterpret_cast<float4*>(out);
        for (int i = gtid; i < (T_STEPS * N_NEUR) / 4; i += NBLK * NTHR) {
            float4 v = sp4[i];
            v.x *= 1.5f; v.y *= 1.5f; v.z *= 1.5f; v.w *= 1.5f;
            out4[i] = v;
        }
        return;
    }

    // ================= Fallback path (correctness only) =================

    // ---- Phase B: input-current GEMM cur[u,t,n] = spikes[t,:].w_in[u,n,:] ----
    for (int idx = gtid; idx < U_UNITS * T_STEPS * N_NEUR; idx += NBLK * NTHR) {
        int u = idx / (T_STEPS * N_NEUR);
        int r = idx % (T_STEPS * N_NEUR);
        int t = r / N_NEUR, n = r % N_NEUR;
        const float* sp = spikes + (size_t)t * N_NEUR;
        const float* wr = w_in + ((size_t)u * N_NEUR + n) * N_NEUR;
        float acc = 0.0f;
        #pragma unroll 4
        for (int k = 0; k < N_NEUR; k++) acc += sp[k] * wr[k];
        g_cur[idx] = acc;
    }

    grid_barrier();

    // ---- Phase C: LIF recurrent scan, blocks 0..15 each own a unit ----
    {
        __shared__ unsigned mask[32];
        __shared__ int s_total;
        if (bid < U_UNITS) {
            const int u = bid, n = tid;
            if (n == 0) s_total = 0;
            const float DTM = 5e-5f, DEC = 1.0f - 1e-4f;
            const float VLEAK = -70.0f, VTH = -55.0f, VRST = -70.0f;
            float v = VLEAK, i_syn = 0.0f;
            int count_prev = 0, emitted = 0;
            const float* wr   = w_rec + ((size_t)u * N_NEUR + n) * N_NEUR;
            const float* curp = g_cur + (size_t)u * T_STEPS * N_NEUR + n;
            uint8_t*     zp   = g_z   + (size_t)u * T_STEPS * N_NEUR + n;
            float cur_t = curp[0];
            __syncthreads();
            for (int t = 0; t < T_STEPS; t++) {
                float v_dec = v + DTM * ((VLEAK - v) + i_syn);
                float i_dec = i_syn * DEC;
                bool  z     = (v_dec - VTH) > 0.0f;
                v = z ? VRST : v_dec;
                emitted += (int)z;
                zp[t * N_NEUR] = z ? (uint8_t)1 : (uint8_t)0;
                float rec = 0.0f;
                if (count_prev > 0) {
                    #pragma unroll 1
                    for (int w = 0; w < 32; w++) {
                        unsigned m = mask[w];
                        while (m) {
                            int b = __ffs(m) - 1;
                            rec += wr[w * 32 + b];
                            m &= m - 1;
                        }
                    }
                }
                i_syn = i_dec + cur_t + rec;
                float cur_next = (t + 1 < T_STEPS) ? curp[(t + 1) * N_NEUR] : 0.0f;
                __syncthreads();
                unsigned bal = __ballot_sync(0xFFFFFFFFu, z);
                if (lane == 0) mask[warp] = bal;
                __syncthreads();
                count_prev = 0;
                #pragma unroll
                for (int w = 0; w < 32; w++) count_prev += __popc(mask[w]);
                cur_t = cur_next;
            }
            g_act[u * N_NEUR + n] = (float)emitted * (1.0f / T_STEPS);
            atomicAdd(&s_total, emitted);
            __syncthreads();
            if (n == 0) g_spk[u] = s_total;
        }
    }

    grid_barrier();

    // ---- Phase D: hidden layer h = relu(act @ cw1.T + cb1), blocks 0..127 ----
    if (bid < H_DIM) {
        const float* row = cw1 + (size_t)bid * (U_UNITS * N_NEUR);
        float s = 0.0f;
        for (int j = tid; j < U_UNITS * N_NEUR; j += NTHR) s += row[j] * g_act[j];
        #pragma unroll
        for (int o = 16; o > 0; o >>= 1) s += __shfl_down_sync(0xFFFFFFFFu, s, o);
        if (lane == 0) s_red[warp] = s;
        __syncthreads();
        if (tid == 0) {
            float v = 0.0f;
            #pragma unroll
            for (int w = 0; w < 32; w++) v += s_red[w];
            g_h[bid] = fmaxf(v + cb1[bid], 0.0f);
        }
    }

    grid_barrier();

    // ---- Phase E: conn matrix + spike total, block 0 ----
    if (bid == 0) {
        __shared__ float hs[H_DIM];
        if (tid < H_DIM) hs[tid] = g_h[tid];
        __syncthreads();
        if (tid < U_UNITS * U_UNITS) {
            const int j = tid;
            float logit = cb2[j];
            const float* row = cw2 + (size_t)j * H_DIM;
            #pragma unroll 4
            for (int k = 0; k < H_DIM; k++) logit += hs[k] * row[k];
            float p = 1.0f / (1.0f + expf(-logit));
            uint32_t c = (j < 128) ? (uint32_t)j : (uint32_t)(j - 128);
            uint32_t o0, o1;
            threefry2x32(0u, 42u, c, c + 128u, o0, o1);
            uint32_t bits = (j < 128) ? o0 : o1;
            float uf = __uint_as_float((bits >> 9) | 0x3F800000u) - 1.0f;
            uf = fmaxf(uf, 0.0f);
            g_conn[j] = (uf < p) ? 1.0f : 0.0f;
            if (j == 0) {
                int tot = 0;
                #pragma unroll
                for (int u2 = 0; u2 < U_UNITS; u2++) tot += g_spk[u2];
                g_spk_total = tot;
            }
        }
    }

    grid_barrier();

    // ---- Phase F: routed/applied/combined + residual ----
    {
        const int zero = (g_spk_total == 0);
        for (int idx = gtid; idx < T_STEPS * N_NEUR; idx += NBLK * NTHR) {
            int t = idx / N_NEUR, m = idx % N_NEUR;
            float c = 0.0f;
            if (!zero) {
                for (int j = 0; j < U_UNITS; j++) {
                    float cj = 0.0f;
                    for (int nn = 0; nn < N_NEUR; nn++) {
                        float r = 0.0f;
                        #pragma unroll
                        for (int i2 = 0; i2 < U_UNITS; i2++)
                            r += g_conn[i2 * U_UNITS + j] *
                                 (float)g_z[((size_t)i2 * T_STEPS + t) * N_NEUR + nn];
                        cj += r * unit_w[((size_t)j * N_NEUR + nn) * N_NEUR + m];
                    }
                    c += cj;
                }
                c *= (1.0f / U_UNITS);
            }
            out[idx] = c + 1.5f * spikes[idx];
        }
    }
}

// ---------------- launch ----------------
extern "C" void kernel_launch(void* const* d_in, const int* in_sizes, int n_in,
                              void* d_out, int out_size) {
    const float* spikes = (const float*)d_in[0];
    const float* w_in   = (const float*)d_in[1];
    const float* w_rec  = (const float*)d_in[2];
    const float* unit_w = (const float*)d_in[3];
    const float* cw1    = (const float*)d_in[4];
    const float* cb1    = (const float*)d_in[5];
    const float* cw2    = (const float*)d_in[6];
    const float* cb2    = (const float*)d_in[7];
    float* out = (float*)d_out;

    mega<<<NBLK, NTHR>>>(spikes, w_in, w_rec, unit_w, cw1, cb1, cw2, cb2, out);
}